// round 1
// baseline (speedup 1.0000x reference)
#include <cuda_runtime.h>

// TransferNet: B=8192 independent sequences, T=1024 steps, C=6 channels.
// s_j(t) = a*feats[b,t,j] + (1-a) * ln( sum_i exp( s_i(t-1) * Tn[i][j] ) ),
// s(0) = feats[b,0,:], out[b,t,:] = s(t).
//
// Mapping: 6 lanes per batch (one per output channel j), 5 groups per warp
// (lanes 30,31 are dummies operating on padding smem slots). State exchange
// via shfl.idx. Global I/O staged through a 64-step smem tile, in-place:
// load coalesced -> recurrence overwrites slots -> store coalesced.

constexpr int T_STEPS = 1024;
constexpr int C       = 6;
constexpr int BPB     = 20;     // batches per block (4 warps * 5 groups)
constexpr int NTHREADS = 128;
constexpr int TT      = 64;     // time tile
constexpr int S_STRIDE = 134;   // words per timestep: 4 warps*32 + 6 pad; 134 % 32 == 6
                                // makes both access patterns bank-conflict-free
constexpr float LOG2E_F = 1.4426950408889634f;
constexpr float LN2_F   = 0.6931471805599453f;

__device__ __forceinline__ float ex2f(float x) {
    float r; asm("ex2.approx.ftz.f32 %0, %1;" : "=f"(r) : "f"(x)); return r;
}
__device__ __forceinline__ float lg2f(float x) {
    float r; asm("lg2.approx.ftz.f32 %0, %1;" : "=f"(r) : "f"(x)); return r;
}

__global__ __launch_bounds__(NTHREADS, 1)
void transfer_kernel(const float* __restrict__ feats,
                     const float* __restrict__ alpha,
                     const float* __restrict__ trans,
                     float* __restrict__ out, int B)
{
    __shared__ float tile[TT * S_STRIDE];

    const int tid  = threadIdx.x;
    const int warp = tid >> 5;
    const int lane = tid & 31;
    int g = lane / 6; if (g > 4) g = 4;       // lanes 30,31 alias group 4 (dummy)
    const int j     = lane - (lane / 6) * 6;  // 0..5 (dummy lanes: 0,1)
    const int gbase = g * 6;
    const int coff  = warp * 32 + lane;       // lanes 30,31 land on pad words

    const int b0 = blockIdx.x * BPB;

    // a = sigmoid(alpha)
    const float av = alpha[0];
    const float a  = 1.0f / (1.0f + __expf(-av));
    const float ia = 1.0f - a;

    // Row-softmax of transitions; keep column j, pre-scaled by log2(e)
    float t2[6];
    #pragma unroll
    for (int i = 0; i < 6; ++i) {
        float row[6], m = -1e30f;
        #pragma unroll
        for (int k = 0; k < 6; ++k) { row[k] = trans[i * 6 + k]; m = fmaxf(m, row[k]); }
        float sum = 0.f, ej = 0.f;
        #pragma unroll
        for (int k = 0; k < 6; ++k) {
            float e = ex2f((row[k] - m) * LOG2E_F);
            sum += e;
            if (k == j) ej = e;
        }
        t2[i] = (ej / sum) * LOG2E_F;
    }

    float s = 0.f;
    const unsigned FULL = 0xffffffffu;

    for (int t0 = 0; t0 < T_STEPS; t0 += TT) {
        // ---- phase 1: coalesced load tile (global -> smem) ----
        #pragma unroll 1
        for (int n = tid; n < BPB * TT * C; n += NTHREADS) {
            int bl = n / (TT * C);
            int k  = n - bl * (TT * C);
            int b  = b0 + bl;
            if (b < B) {
                int tt = k / C, c = k - tt * C;
                tile[tt * S_STRIDE + (bl / 5) * 32 + (bl % 5) * 6 + c] =
                    feats[(size_t)b * (T_STEPS * C) + (size_t)(t0 + tt) * C + c];
            }
        }
        __syncthreads();

        // ---- phase 2: recurrence over this tile (in-place) ----
        int tstart = 0;
        if (t0 == 0) { s = tile[coff]; tstart = 1; }  // t=0: state = feats, output unchanged

        #pragma unroll 4
        for (int tt = tstart; tt < TT; ++tt) {
            float s0 = __shfl_sync(FULL, s, gbase + 0);
            float s1 = __shfl_sync(FULL, s, gbase + 1);
            float s2 = __shfl_sync(FULL, s, gbase + 2);
            float s3 = __shfl_sync(FULL, s, gbase + 3);
            float s4 = __shfl_sync(FULL, s, gbase + 4);
            float s5 = __shfl_sync(FULL, s, gbase + 5);
            float cur = tile[tt * S_STRIDE + coff];
            float e0 = ex2f(s0 * t2[0]);
            float e1 = ex2f(s1 * t2[1]);
            float e2 = ex2f(s2 * t2[2]);
            float e3 = ex2f(s3 * t2[3]);
            float e4 = ex2f(s4 * t2[4]);
            float e5 = ex2f(s5 * t2[5]);
            float acc = ((e0 + e1) + (e2 + e3)) + (e4 + e5);
            float te  = lg2f(acc) * LN2_F;
            s = a * cur + ia * te;
            tile[tt * S_STRIDE + coff] = s;
        }
        __syncthreads();

        // ---- phase 3: coalesced store tile (smem -> global) ----
        #pragma unroll 1
        for (int n = tid; n < BPB * TT * C; n += NTHREADS) {
            int bl = n / (TT * C);
            int k  = n - bl * (TT * C);
            int b  = b0 + bl;
            if (b < B) {
                int tt = k / C, c = k - tt * C;
                out[(size_t)b * (T_STEPS * C) + (size_t)(t0 + tt) * C + c] =
                    tile[tt * S_STRIDE + (bl / 5) * 32 + (bl % 5) * 6 + c];
            }
        }
        __syncthreads();
    }
}

extern "C" void kernel_launch(void* const* d_in, const int* in_sizes, int n_in,
                              void* d_out, int out_size) {
    const float* feats = (const float*)d_in[0];
    const float* alpha = (const float*)d_in[1];
    const float* trans = (const float*)d_in[2];
    float* out = (float*)d_out;
    (void)n_in; (void)out_size;

    int B = in_sizes[0] / (T_STEPS * C);
    int grid = (B + BPB - 1) / BPB;
    transfer_kernel<<<grid, NTHREADS>>>(feats, alpha, trans, out, B);
}

// round 2
// speedup vs baseline: 5.1908x; 5.1908x over previous
#include <cuda_runtime.h>

// TransferNet: B=8192 independent sequences, T=1024 steps, C=6 channels.
// s_j(t) = a*feats[b,t,j] + (1-a)*ln( sum_i exp( s_i(t-1)*Tn[i][j] ) )
// s(0) = feats[b,0,:], out[b,t,:] = s(t).
//
// Mapping: 6 lanes per batch (one per channel j), 5 groups/warp, 4 warps/block
// -> 20 batches/block. State exchange via shfl.idx. Global I/O staged through
// a 64-step smem tile, in-place (load coalesced -> compute overwrites ->
// store coalesced). Copy loops are fully unrolled with hoisted index math:
// 384 = 3*128 so each thread's intra-chunk offsets are {tid, tid+128, tid+256},
// constant for the whole kernel; per-element cost is 1 LDG + 1 STS.

constexpr int T_STEPS  = 1024;
constexpr int C        = 6;
constexpr int BPB      = 20;    // batches per block (4 warps * 5 groups)
constexpr int NTHREADS = 128;
constexpr int TT       = 64;    // time tile
constexpr int ROW      = T_STEPS * C;     // 6144 floats per batch
constexpr int CHUNK    = TT * C;          // 384 floats per (batch, tile)
constexpr int S_STRIDE = 134;   // 134 % 32 == 6 -> conflict-free everywhere
constexpr float LOG2E_F = 1.4426950408889634f;
constexpr float LN2_F   = 0.6931471805599453f;

__device__ __forceinline__ float ex2f(float x) {
    float r; asm("ex2.approx.ftz.f32 %0, %1;" : "=f"(r) : "f"(x)); return r;
}
__device__ __forceinline__ float lg2f(float x) {
    float r; asm("lg2.approx.ftz.f32 %0, %1;" : "=f"(r) : "f"(x)); return r;
}

__global__ __launch_bounds__(NTHREADS, 1)
void transfer_kernel(const float* __restrict__ feats,
                     const float* __restrict__ alpha,
                     const float* __restrict__ trans,
                     float* __restrict__ out, int B)
{
    __shared__ float tile[TT * S_STRIDE];

    const int tid  = threadIdx.x;
    const int warp = tid >> 5;
    const int lane = tid & 31;
    int g = lane / 6; if (g > 4) g = 4;       // lanes 30,31: dummies on pad slots
    const int j     = lane - (lane / 6) * 6;
    const int gbase = g * 6;
    const int coff  = warp * 32 + lane;

    const int b0 = blockIdx.x * BPB;
    int nvalid = B - b0; if (nvalid > BPB) nvalid = BPB;

    // a = sigmoid(alpha)
    const float av = alpha[0];
    const float a  = 1.0f / (1.0f + __expf(-av));
    const float ia = 1.0f - a;

    // Row-softmax of transitions; keep column j, pre-scaled by log2(e)
    float t2[6];
    #pragma unroll
    for (int i = 0; i < 6; ++i) {
        float row[6], m = -1e30f;
        #pragma unroll
        for (int k = 0; k < 6; ++k) { row[k] = trans[i * 6 + k]; m = fmaxf(m, row[k]); }
        float sum = 0.f, ej = 0.f;
        #pragma unroll
        for (int k = 0; k < 6; ++k) {
            float e = ex2f((row[k] - m) * LOG2E_F);
            sum += e;
            if (k == j) ej = e;
        }
        t2[i] = (ej / sum) * LOG2E_F;
    }

    // Per-thread copy offsets (constant for the whole kernel).
    // Element n = tid + 128*k of a tile; since CHUNK=384=3*128, the intra-chunk
    // offsets are exactly {tid, tid+128, tid+256} and bl = k/3.
    const int r0 = tid, r1 = tid + 128, r2 = tid + 256;
    const int s0 = (r0 / 6) * S_STRIDE + (r0 % 6);
    const int s1 = (r1 / 6) * S_STRIDE + (r1 % 6);
    const int s2 = (r2 / 6) * S_STRIDE + (r2 % 6);

    float s = 0.f;
    const unsigned FULL = 0xffffffffu;

    for (int t0 = 0; t0 < T_STEPS; t0 += TT) {
        const size_t gofs = (size_t)b0 * ROW + (size_t)t0 * C;
        const float* gsrc = feats + gofs;

        // ---- phase 1: coalesced load (global -> smem), fully unrolled ----
        #pragma unroll
        for (int bl = 0; bl < BPB; ++bl) {
            const int sb = (bl / 5) * 32 + (bl % 5) * 6;   // compile-time
            if (bl < nvalid) {
                const float* gp = gsrc + bl * ROW;
                tile[s0 + sb] = gp[r0];
                tile[s1 + sb] = gp[r1];
                tile[s2 + sb] = gp[r2];
            }
        }
        __syncthreads();

        // ---- phase 2: recurrence over this tile (in-place) ----
        int tstart = 0;
        if (t0 == 0) { s = tile[coff]; tstart = 1; }  // t=0: state = feats

        #pragma unroll 4
        for (int tt = tstart; tt < TT; ++tt) {
            float v0 = __shfl_sync(FULL, s, gbase + 0);
            float v1 = __shfl_sync(FULL, s, gbase + 1);
            float v2 = __shfl_sync(FULL, s, gbase + 2);
            float v3 = __shfl_sync(FULL, s, gbase + 3);
            float v4 = __shfl_sync(FULL, s, gbase + 4);
            float v5 = __shfl_sync(FULL, s, gbase + 5);
            float cur = tile[tt * S_STRIDE + coff];
            float e0 = ex2f(v0 * t2[0]);
            float e1 = ex2f(v1 * t2[1]);
            float e2 = ex2f(v2 * t2[2]);
            float e3 = ex2f(v3 * t2[3]);
            float e4 = ex2f(v4 * t2[4]);
            float e5 = ex2f(v5 * t2[5]);
            float acc = ((e0 + e1) + (e2 + e3)) + (e4 + e5);
            float te  = lg2f(acc) * LN2_F;
            s = a * cur + ia * te;
            tile[tt * S_STRIDE + coff] = s;
        }
        __syncthreads();

        // ---- phase 3: coalesced store (smem -> global), fully unrolled ----
        float* gdst = out + gofs;
        #pragma unroll
        for (int bl = 0; bl < BPB; ++bl) {
            const int sb = (bl / 5) * 32 + (bl % 5) * 6;   // compile-time
            if (bl < nvalid) {
                float* gp = gdst + bl * ROW;
                gp[r0] = tile[s0 + sb];
                gp[r1] = tile[s1 + sb];
                gp[r2] = tile[s2 + sb];
            }
        }
        __syncthreads();
    }
}

extern "C" void kernel_launch(void* const* d_in, const int* in_sizes, int n_in,
                              void* d_out, int out_size) {
    const float* feats = (const float*)d_in[0];
    const float* alpha = (const float*)d_in[1];
    const float* trans = (const float*)d_in[2];
    float* out = (float*)d_out;
    (void)n_in; (void)out_size;

    int B = in_sizes[0] / (T_STEPS * C);
    int grid = (B + BPB - 1) / BPB;
    transfer_kernel<<<grid, NTHREADS>>>(feats, alpha, trans, out, B);
}